// round 2
// baseline (speedup 1.0000x reference)
#include <cuda_runtime.h>
#include <cstdint>

// out[b, f] = (medians[f] > 0 && inputs[b, f] >= medians[f]) ? 1.0f : 0.0f
// inputs: 8192 x 4096 fp32 (134 MB streamed), medians: 4096 fp32 (L2-resident),
// output: float32 (134 MB streamed).  Pure HBM-bound elementwise kernel.
//
// Each thread: 4x float4 loads + 4x float4 stores (64 B in, 64 B out).
// Row width 4096 % 16 == 0 so a thread never crosses a row; the median
// index is (element_index & 4095) and the 16 KB median table stays hot in L1/L2.

#define ROW 4096
#define ROW4 (ROW / 4)  // 1024 float4 per row

__device__ __forceinline__ float4 cmp4(float4 a, float4 m) {
    float4 r;
    r.x = (m.x > 0.0f && a.x >= m.x) ? 1.0f : 0.0f;
    r.y = (m.y > 0.0f && a.y >= m.y) ? 1.0f : 0.0f;
    r.z = (m.z > 0.0f && a.z >= m.z) ? 1.0f : 0.0f;
    r.w = (m.w > 0.0f && a.w >= m.w) ? 1.0f : 0.0f;
    return r;
}

__global__ void __launch_bounds__(256)
binarize_kernel(const float4* __restrict__ in,
                const float4* __restrict__ med,
                float4* __restrict__ out) {
    unsigned t = blockIdx.x * blockDim.x + threadIdx.x;
    size_t base4 = (size_t)t * 4;                    // float4 index
    unsigned col4 = (unsigned)(base4 & (ROW4 - 1));  // float4-column within row

    // 4 independent loads issued up-front -> MLP of 4 per thread.
    float4 a0 = in[base4 + 0];
    float4 a1 = in[base4 + 1];
    float4 a2 = in[base4 + 2];
    float4 a3 = in[base4 + 3];

    float4 m0 = med[col4 + 0];
    float4 m1 = med[col4 + 1];
    float4 m2 = med[col4 + 2];
    float4 m3 = med[col4 + 3];

    out[base4 + 0] = cmp4(a0, m0);
    out[base4 + 1] = cmp4(a1, m1);
    out[base4 + 2] = cmp4(a2, m2);
    out[base4 + 3] = cmp4(a3, m3);
}

extern "C" void kernel_launch(void* const* d_in, const int* in_sizes, int n_in,
                              void* d_out, int out_size) {
    // Defensive: pick the larger tensor as `inputs`, the smaller as `medians`.
    int ii = 0, mi = 1;
    if (n_in >= 2 && in_sizes[1] > in_sizes[0]) { ii = 1; mi = 0; }

    const float4* in  = (const float4*)d_in[ii];   // 8192*4096 fp32
    const float4* med = (const float4*)d_in[mi];   // 4096 fp32
    float4* out = (float4*)d_out;                  // float32 0/1

    long long n = (long long)in_sizes[ii];         // 33,554,432 elements
    long long threads_total = n / 16;              // 2,097,152
    int block = 256;
    long long grid = threads_total / block;        // 8192, exact cover
    binarize_kernel<<<(unsigned)grid, block>>>(in, med, out);
}

// round 6
// speedup vs baseline: 1.3050x; 1.3050x over previous
#include <cuda_runtime.h>
#include <cstdint>

// out[b, f] = (medians[f] > 0 && inputs[b, f] >= medians[f]) ? 1.0f : 0.0f
// inputs: 8192 x 4096 fp32 (134 MB streamed), medians: 4096 fp32,
// output: float32 (134 MB streamed). Pure HBM-bound elementwise kernel.
//
// Column-tiled: block of 256 threads owns 256 consecutive float4 columns
// (quarter row). Every warp load/store is 512 B *contiguous* -> minimum L1
// wavefronts (R2's 64B-strided layout caused 4x amplification, L1 81%).
// Each thread keeps its median float4 in registers and walks RGRP rows,
// unrolled x4 so 4 independent loads are in flight (MLP = 4).

#define ROW4   1024   // float4 per row (4096 floats)
#define COLS4  256    // float4 columns per block (= blockDim.x)
#define RGRP   8      // rows per block
#define NROWS  8192

__device__ __forceinline__ float4 cmp4(float4 a, float4 m) {
    float4 r;
    r.x = (m.x > 0.0f && a.x >= m.x) ? 1.0f : 0.0f;
    r.y = (m.y > 0.0f && a.y >= m.y) ? 1.0f : 0.0f;
    r.z = (m.z > 0.0f && a.z >= m.z) ? 1.0f : 0.0f;
    r.w = (m.w > 0.0f && a.w >= m.w) ? 1.0f : 0.0f;
    return r;
}

__global__ void __launch_bounds__(COLS4)
binarize_kernel(const float4* __restrict__ in,
                const float4* __restrict__ med,
                float4* __restrict__ out) {
    // 4 column-groups per row; row-groups in the upper grid bits.
    unsigned cg   = blockIdx.x & 3u;           // which quarter of the row
    unsigned rg   = blockIdx.x >> 2;           // row group
    unsigned col4 = cg * COLS4 + threadIdx.x;
    size_t   base = (size_t)rg * RGRP * ROW4 + col4;

    const float4 m = med[col4];                // register-resident across rows

    #pragma unroll
    for (int r = 0; r < RGRP; r += 4) {
        size_t i0 = base + (size_t)(r + 0) * ROW4;
        size_t i1 = base + (size_t)(r + 1) * ROW4;
        size_t i2 = base + (size_t)(r + 2) * ROW4;
        size_t i3 = base + (size_t)(r + 3) * ROW4;

        // 4 independent loads in flight before any store (MLP = 4).
        float4 a0 = in[i0];
        float4 a1 = in[i1];
        float4 a2 = in[i2];
        float4 a3 = in[i3];

        out[i0] = cmp4(a0, m);
        out[i1] = cmp4(a1, m);
        out[i2] = cmp4(a2, m);
        out[i3] = cmp4(a3, m);
    }
}

extern "C" void kernel_launch(void* const* d_in, const int* in_sizes, int n_in,
                              void* d_out, int out_size) {
    // Defensive: larger tensor = inputs, smaller = medians.
    int ii = 0, mi = 1;
    if (n_in >= 2 && in_sizes[1] > in_sizes[0]) { ii = 1; mi = 0; }

    const float4* in  = (const float4*)d_in[ii];
    const float4* med = (const float4*)d_in[mi];
    float4* out = (float4*)d_out;

    // 4 col-groups x (8192 / RGRP) row-groups = 4096 blocks of 256 threads.
    unsigned grid = 4u * (NROWS / RGRP);
    binarize_kernel<<<grid, COLS4>>>(in, med, out);
}

// round 7
// speedup vs baseline: 1.3113x; 1.0048x over previous
#include <cuda_runtime.h>
#include <cstdint>

// out[b, f] = (medians[f] > 0 && inputs[b, f] >= medians[f]) ? 1.0f : 0.0f
// inputs: 8192 x 4096 fp32 (134 MB streamed), medians: 4096 fp32,
// output: float32 (134 MB streamed). Pure HBM-bound elementwise kernel.
//
// Column-tiled (R6 layout, L1-optimal): block of 256 threads owns 256
// consecutive float4 columns; every warp access is 512 B contiguous.
// New in R7:
//   - software-pipelined double buffer: next 4 rows' loads are issued
//     BEFORE this group's stores, so stores never wait on freshly-issued
//     loads (exposed DRAM latency halved per thread).
//   - __ldcs/__stcs streaming hints: both streams have zero reuse;
//     evict-first keeps them from thrashing L2.
//   - RGRP=16 -> 2048 blocks, median loaded once per thread.

#define ROW4   1024   // float4 per row (4096 floats)
#define COLS4  256    // float4 columns per block (= blockDim.x)
#define RGRP   16     // rows per block
#define NROWS  8192

__device__ __forceinline__ float4 cmp4(float4 a, float4 m) {
    float4 r;
    r.x = (m.x > 0.0f && a.x >= m.x) ? 1.0f : 0.0f;
    r.y = (m.y > 0.0f && a.y >= m.y) ? 1.0f : 0.0f;
    r.z = (m.z > 0.0f && a.z >= m.z) ? 1.0f : 0.0f;
    r.w = (m.w > 0.0f && a.w >= m.w) ? 1.0f : 0.0f;
    return r;
}

__global__ void __launch_bounds__(COLS4)
binarize_kernel(const float4* __restrict__ in,
                const float4* __restrict__ med,
                float4* __restrict__ out) {
    unsigned cg   = blockIdx.x & 3u;           // quarter of the row
    unsigned rg   = blockIdx.x >> 2;           // row group
    unsigned col4 = cg * COLS4 + threadIdx.x;
    size_t   base = (size_t)rg * RGRP * ROW4 + col4;

    const float4 m = med[col4];                // register-resident across rows

    // Prologue: load rows 0..3.
    float4 a0 = __ldcs(&in[base + 0 * ROW4]);
    float4 a1 = __ldcs(&in[base + 1 * ROW4]);
    float4 a2 = __ldcs(&in[base + 2 * ROW4]);
    float4 a3 = __ldcs(&in[base + 3 * ROW4]);

    #pragma unroll
    for (int r = 0; r < RGRP - 4; r += 4) {
        size_t nb = base + (size_t)(r + 4) * ROW4;
        // Issue next group's loads BEFORE this group's stores.
        float4 b0 = __ldcs(&in[nb + 0 * ROW4]);
        float4 b1 = __ldcs(&in[nb + 1 * ROW4]);
        float4 b2 = __ldcs(&in[nb + 2 * ROW4]);
        float4 b3 = __ldcs(&in[nb + 3 * ROW4]);

        size_t sb = base + (size_t)r * ROW4;
        __stcs(&out[sb + 0 * ROW4], cmp4(a0, m));
        __stcs(&out[sb + 1 * ROW4], cmp4(a1, m));
        __stcs(&out[sb + 2 * ROW4], cmp4(a2, m));
        __stcs(&out[sb + 3 * ROW4], cmp4(a3, m));

        a0 = b0; a1 = b1; a2 = b2; a3 = b3;
    }

    // Epilogue: store last 4 rows.
    size_t sb = base + (size_t)(RGRP - 4) * ROW4;
    __stcs(&out[sb + 0 * ROW4], cmp4(a0, m));
    __stcs(&out[sb + 1 * ROW4], cmp4(a1, m));
    __stcs(&out[sb + 2 * ROW4], cmp4(a2, m));
    __stcs(&out[sb + 3 * ROW4], cmp4(a3, m));
}

extern "C" void kernel_launch(void* const* d_in, const int* in_sizes, int n_in,
                              void* d_out, int out_size) {
    // Defensive: larger tensor = inputs, smaller = medians.
    int ii = 0, mi = 1;
    if (n_in >= 2 && in_sizes[1] > in_sizes[0]) { ii = 1; mi = 0; }

    const float4* in  = (const float4*)d_in[ii];
    const float4* med = (const float4*)d_in[mi];
    float4* out = (float4*)d_out;

    // 4 col-groups x (8192 / RGRP) row-groups = 2048 blocks of 256 threads.
    unsigned grid = 4u * (NROWS / RGRP);
    binarize_kernel<<<grid, COLS4>>>(in, med, out);
}